// round 1
// baseline (speedup 1.0000x reference)
#include <cuda_runtime.h>
#include <cuda_bf16.h>
#include <cstddef>

// ---------------------------------------------------------------------------
// StructureAttention: x[4,16384,256]
//   q=phi(xWq) k=phi(xWk) v=xWv  (phi = elu+1)
//   KV[n,h] = sum_l k (x) v      Ksum[n,h] = sum_l k
//   msg = (Q @ KV) / (Q . Ksum + 1e-6)          (L-scalings cancel exactly)
//   msg = LN1(msg @ Wm); h = relu([x,msg] @ W1); out = x + LN2(h @ W2)
// ---------------------------------------------------------------------------

#define C_DIM 256
#define NB    4

// scratch buffers (64MB each) + small reduction scratch
__device__ float g_bufQ[16777216];
__device__ float g_bufK[16777216];
__device__ float g_bufV[16777216];
__device__ float g_small[32 * 1024 + 32 * 32]; // KV[32][32][32] then Ksum[32][32]

// ---------------------------------------------------------------------------
// epilogue functors
// ---------------------------------------------------------------------------
template <int EPI>
__device__ __forceinline__ float epi(float t) {
    if (EPI == 1) return t > 0.f ? t + 1.f : __expf(t);   // phi = elu(t)+1
    if (EPI == 2) return fmaxf(t, 0.f);                   // relu
    return t;
}

// ---------------------------------------------------------------------------
// SGEMM: C[M,256] = A[M,K] * B[K,256] ; K = 256 or 512.
// For K=512, A logical = concat(A0, A1) along K (each [M,256]).
// BM=BN=128, BK=8, 256 threads, 8x8 per-thread tile, double-buffered smem.
// ---------------------------------------------------------------------------
template <int K, int EPI>
__global__ __launch_bounds__(256) void sgemm_kernel(
    const float* __restrict__ A0, const float* __restrict__ A1,
    const float* __restrict__ B, float* __restrict__ Cout)
{
    __shared__ float As[2][8][128];
    __shared__ float Bs[2][8][128];

    const int tid = threadIdx.x;
    const int m0 = blockIdx.y * 128;
    const int n0 = blockIdx.x * 128;

    const int tx = tid & 15;   // 0..15
    const int ty = tid >> 4;   // 0..15

    const int a_row = tid >> 1;         // 0..127
    const int a_col = (tid & 1) * 4;    // 0 or 4
    const int b_row = tid >> 5;         // 0..7
    const int b_col = (tid & 31) * 4;   // 0..124

    float acc[8][8];
#pragma unroll
    for (int i = 0; i < 8; ++i)
#pragma unroll
        for (int j = 0; j < 8; ++j) acc[i][j] = 0.f;

    float4 aReg, bReg;

    // prologue: tile 0
    {
        int kg = a_col;
        const float* Ap = A0; int kk = kg;
        if (K == 512 && kg >= 256) { Ap = A1; kk = kg - 256; }
        aReg = *(const float4*)&Ap[(size_t)(m0 + a_row) * 256 + kk];
        bReg = *(const float4*)&B[(size_t)b_row * 256 + n0 + b_col];
    }
    As[0][a_col + 0][a_row] = aReg.x;
    As[0][a_col + 1][a_row] = aReg.y;
    As[0][a_col + 2][a_row] = aReg.z;
    As[0][a_col + 3][a_row] = aReg.w;
    *(float4*)&Bs[0][b_row][b_col] = bReg;
    __syncthreads();

    const int nK = K / 8;
    for (int kt = 0; kt < nK; ++kt) {
        const int cur = kt & 1;
        if (kt + 1 < nK) {
            int kg = (kt + 1) * 8 + a_col;
            const float* Ap = A0; int kk = kg;
            if (K == 512 && kg >= 256) { Ap = A1; kk = kg - 256; }
            aReg = *(const float4*)&Ap[(size_t)(m0 + a_row) * 256 + kk];
            bReg = *(const float4*)&B[(size_t)((kt + 1) * 8 + b_row) * 256 + n0 + b_col];
        }
#pragma unroll
        for (int k = 0; k < 8; ++k) {
            float4 a0 = *(const float4*)&As[cur][k][ty * 4];
            float4 a1 = *(const float4*)&As[cur][k][64 + ty * 4];
            float4 b0 = *(const float4*)&Bs[cur][k][tx * 4];
            float4 b1 = *(const float4*)&Bs[cur][k][64 + tx * 4];
            float a[8] = {a0.x, a0.y, a0.z, a0.w, a1.x, a1.y, a1.z, a1.w};
            float b[8] = {b0.x, b0.y, b0.z, b0.w, b1.x, b1.y, b1.z, b1.w};
#pragma unroll
            for (int i = 0; i < 8; ++i)
#pragma unroll
                for (int j = 0; j < 8; ++j) acc[i][j] += a[i] * b[j];
        }
        if (kt + 1 < nK) {
            const int nxt = cur ^ 1;
            As[nxt][a_col + 0][a_row] = aReg.x;
            As[nxt][a_col + 1][a_row] = aReg.y;
            As[nxt][a_col + 2][a_row] = aReg.z;
            As[nxt][a_col + 3][a_row] = aReg.w;
            *(float4*)&Bs[nxt][b_row][b_col] = bReg;
            __syncthreads();
        }
    }

    // epilogue
#pragma unroll
    for (int i = 0; i < 8; ++i) {
        int r = m0 + ((i < 4) ? ty * 4 + i : 64 + ty * 4 + (i - 4));
        float4 o0, o1;
        o0.x = epi<EPI>(acc[i][0]); o0.y = epi<EPI>(acc[i][1]);
        o0.z = epi<EPI>(acc[i][2]); o0.w = epi<EPI>(acc[i][3]);
        o1.x = epi<EPI>(acc[i][4]); o1.y = epi<EPI>(acc[i][5]);
        o1.z = epi<EPI>(acc[i][6]); o1.w = epi<EPI>(acc[i][7]);
        *(float4*)&Cout[(size_t)r * 256 + n0 + tx * 4] = o0;
        *(float4*)&Cout[(size_t)r * 256 + n0 + 64 + tx * 4] = o1;
    }
}

// ---------------------------------------------------------------------------
// zero small scratch
// ---------------------------------------------------------------------------
__global__ void zero_kernel(float* p, int n)
{
    int i = blockIdx.x * blockDim.x + threadIdx.x;
    if (i < n) p[i] = 0.f;
}

// ---------------------------------------------------------------------------
// KV[n,h,d,e] = sum_l K[n,l,h*32+d] * V[n,l,h*32+e] ; Ksum[n,h,d] = sum_l K.
// grid = (32 [n*8+h], 64 splits), 1024 threads: thread=(d,e).
// ---------------------------------------------------------------------------
__global__ __launch_bounds__(1024) void kv_reduce_kernel(
    const float* __restrict__ Kp, const float* __restrict__ Vp,
    float* __restrict__ KV, float* __restrict__ Ksum, int L)
{
    const int nh = blockIdx.x;             // 0..31
    const int n  = nh >> 3;
    const int h  = nh & 7;
    const int rows = L / gridDim.y;        // 256
    const int l0 = blockIdx.y * rows;

    const int tid = threadIdx.x;
    const int d = tid >> 5;
    const int e = tid & 31;

    __shared__ float sk[16][32];
    __shared__ float sv[16][32];

    const size_t base = (size_t)n * L * 256 + h * 32;
    const int ldrow = tid >> 6;        // 0..15
    const int ldc   = tid & 63;        // 0..63

    float acc = 0.f, ks = 0.f;

    for (int l = l0; l < l0 + rows; l += 16) {
        __syncthreads();
        {
            size_t off = base + (size_t)(l + ldrow) * 256;
            if (ldc < 32) sk[ldrow][ldc] = Kp[off + ldc];
            else          sv[ldrow][ldc - 32] = Vp[off + ldc - 32];
        }
        __syncthreads();
#pragma unroll
        for (int r = 0; r < 16; ++r) {
            acc += sk[r][d] * sv[r][e];
        }
        if (e == 0) {
#pragma unroll
            for (int r = 0; r < 16; ++r) ks += sk[r][d];
        }
    }
    atomicAdd(&KV[(size_t)nh * 1024 + d * 32 + e], acc);
    if (e == 0) atomicAdd(&Ksum[nh * 32 + d], ks);
}

// ---------------------------------------------------------------------------
// msg[row, h*32+e] = (sum_d Q[row,h*32+d]*KV[n,h,d,e]) / (Q[row,h,:].Ksum[n,h,:]+1e-6)
// one block (256 threads) per row; thread = (h=warp, e=lane)
// ---------------------------------------------------------------------------
__global__ __launch_bounds__(256) void msg_kernel(
    const float* __restrict__ Q, const float* __restrict__ KV,
    const float* __restrict__ Ksum, float* __restrict__ MSG, int L)
{
    const int row = blockIdx.x;   // n*L + l
    const int n = row / L;
    const int tid = threadIdx.x;
    const int h = tid >> 5;
    const int e = tid & 31;

    __shared__ float qs[256];
    qs[tid] = Q[(size_t)row * 256 + tid];
    __syncthreads();

    float p = qs[h * 32 + e] * Ksum[(n * 8 + h) * 32 + e];
#pragma unroll
    for (int o = 16; o; o >>= 1) p += __shfl_xor_sync(0xffffffffu, p, o);
    const float z = 1.f / (p + 1e-6f);

    const float* kv = KV + (size_t)(n * 8 + h) * 1024;
    float acc = 0.f;
#pragma unroll
    for (int dd = 0; dd < 32; ++dd)
        acc += qs[h * 32 + dd] * kv[dd * 32 + e];

    MSG[(size_t)row * 256 + tid] = acc * z;
}

// ---------------------------------------------------------------------------
// LayerNorm over C=256, optional residual add. One warp per row.
// ---------------------------------------------------------------------------
__global__ __launch_bounds__(256) void ln_kernel(
    const float* __restrict__ in, const float* __restrict__ res,
    const float* __restrict__ g, const float* __restrict__ b,
    float* __restrict__ out, int rows)
{
    const int gw = (int)((blockIdx.x * blockDim.x + threadIdx.x) >> 5);
    if (gw >= rows) return;
    const int lane = threadIdx.x & 31;

    const float4* rp = (const float4*)(in + (size_t)gw * 256);
    float v[8];
    *(float4*)&v[0] = rp[lane];
    *(float4*)&v[4] = rp[lane + 32];

    float s = 0.f;
#pragma unroll
    for (int i = 0; i < 8; ++i) s += v[i];
#pragma unroll
    for (int o = 16; o; o >>= 1) s += __shfl_xor_sync(0xffffffffu, s, o);
    const float mu = s * (1.f / 256.f);

    float vs = 0.f;
#pragma unroll
    for (int i = 0; i < 8; ++i) { v[i] -= mu; vs += v[i] * v[i]; }
#pragma unroll
    for (int o = 16; o; o >>= 1) vs += __shfl_xor_sync(0xffffffffu, vs, o);
    const float rstd = rsqrtf(vs * (1.f / 256.f) + 1e-5f);

    float G[8], Bv[8];
    *(float4*)&G[0]  = ((const float4*)g)[lane];
    *(float4*)&G[4]  = ((const float4*)g)[lane + 32];
    *(float4*)&Bv[0] = ((const float4*)b)[lane];
    *(float4*)&Bv[4] = ((const float4*)b)[lane + 32];

    float o8[8];
#pragma unroll
    for (int i = 0; i < 8; ++i) o8[i] = v[i] * rstd * G[i] + Bv[i];

    if (res) {
        const float4* xp = (const float4*)(res + (size_t)gw * 256);
        float r8[8];
        *(float4*)&r8[0] = xp[lane];
        *(float4*)&r8[4] = xp[lane + 32];
#pragma unroll
        for (int i = 0; i < 8; ++i) o8[i] += r8[i];
    }

    float4* op = (float4*)(out + (size_t)gw * 256);
    op[lane]      = *(float4*)&o8[0];
    op[lane + 32] = *(float4*)&o8[4];
}

// ---------------------------------------------------------------------------
// launch
// ---------------------------------------------------------------------------
extern "C" void kernel_launch(void* const* d_in, const int* in_sizes, int n_in,
                              void* d_out, int out_size)
{
    const float* x  = (const float*)d_in[0];
    const float* Wq = (const float*)d_in[1];
    const float* Wk = (const float*)d_in[2];
    const float* Wv = (const float*)d_in[3];
    const float* Wm = (const float*)d_in[4];
    const float* W1 = (const float*)d_in[5];
    const float* W2 = (const float*)d_in[6];
    const float* g1 = (const float*)d_in[7];
    const float* b1 = (const float*)d_in[8];
    const float* g2 = (const float*)d_in[9];
    const float* b2 = (const float*)d_in[10];

    const int M = in_sizes[0] / C_DIM;   // N*L = 65536
    const int L = M / NB;                // 16384

    float *Qb, *Kb, *Vb, *sm;
    cudaGetSymbolAddress((void**)&Qb, g_bufQ);
    cudaGetSymbolAddress((void**)&Kb, g_bufK);
    cudaGetSymbolAddress((void**)&Vb, g_bufV);
    cudaGetSymbolAddress((void**)&sm, g_small);
    float* KV   = sm;
    float* Ksum = sm + 32 * 1024;

    dim3 gg(C_DIM / 128, M / 128);

    // q = phi(x Wq), k = phi(x Wk), v = x Wv
    sgemm_kernel<256, 1><<<gg, 256>>>(x, nullptr, Wq, Qb);
    sgemm_kernel<256, 1><<<gg, 256>>>(x, nullptr, Wk, Kb);
    sgemm_kernel<256, 0><<<gg, 256>>>(x, nullptr, Wv, Vb);

    // KV / Ksum reduction
    zero_kernel<<<(33792 + 255) / 256, 256>>>(sm, 33792);
    kv_reduce_kernel<<<dim3(32, 64), 1024>>>(Kb, Vb, KV, Ksum, L);

    // msg (writes into Vb; V data already consumed)
    msg_kernel<<<M, 256>>>(Qb, KV, Ksum, Vb, L);

    // msg @ Wm -> Kb ; LN1 -> Qb
    sgemm_kernel<256, 0><<<gg, 256>>>(Vb, nullptr, Wm, Kb);
    ln_kernel<<<M / 8, 256>>>(Kb, nullptr, g1, b1, Qb, M);

    // relu([x, msg1] @ W1) -> Kb
    sgemm_kernel<512, 2><<<gg, 256>>>(x, Qb, W1, Kb);

    // (h @ W2) -> Vb ; out = x + LN2(.)
    sgemm_kernel<256, 0><<<gg, 256>>>(Kb, nullptr, W2, Vb);
    ln_kernel<<<M / 8, 256>>>(Vb, x, g2, b2, (float*)d_out, M);
}

// round 3
// speedup vs baseline: 1.4649x; 1.4649x over previous
#include <cuda_runtime.h>
#include <cuda_bf16.h>
#include <cstdint>
#include <cstddef>

// ===========================================================================
// StructureAttention, tensor cores via mma.sync (bf16 hi/lo x3, fp32 accum).
// (tcgen05 unavailable: harness PTX target is compute_103 w/o 'a' features.)
// ===========================================================================

#define C_DIM 256
#define NB    4
#define MTOT  16777216

__device__ float g_Q[MTOT];
__device__ float g_K[MTOT];
__device__ float g_V[MTOT];
__device__ __nv_bfloat16 g_xhi[MTOT], g_xlo[MTOT];
__device__ __nv_bfloat16 g_mhi[MTOT], g_mlo[MTOT];
__device__ __nv_bfloat16 g_lhi[MTOT], g_llo[MTOT];
__device__ __nv_bfloat16 g_hhi[MTOT], g_hlo[MTOT];
__device__ __nv_bfloat16 g_w[917504];
__device__ float g_small[32 * 1024 + 32 * 32];

// ---------------- helpers --------------------------------------------------
__device__ __forceinline__ uint32_t smem_u32(const void* p) {
    uint32_t a;
    asm("{ .reg .u64 t; cvta.to.shared.u64 t, %1; cvt.u32.u64 %0, t; }" : "=r"(a) : "l"(p));
    return a;
}
__device__ __forceinline__ void cp16(uint32_t dst, const void* src) {
    asm volatile("cp.async.cg.shared.global [%0], [%1], 16;"
                 :: "r"(dst), "l"(__cvta_generic_to_global(src)) : "memory");
}
#define CP_COMMIT() asm volatile("cp.async.commit_group;" ::: "memory")
#define CP_WAIT1()  asm volatile("cp.async.wait_group 1;"  ::: "memory")

__device__ __forceinline__ void ldsm4(uint32_t* r, uint32_t addr) {
    asm volatile("ldmatrix.sync.aligned.m8n8.x4.shared.b16 {%0,%1,%2,%3}, [%4];"
                 : "=r"(r[0]), "=r"(r[1]), "=r"(r[2]), "=r"(r[3]) : "r"(addr));
}
__device__ __forceinline__ void mma_bf16(float* c, const uint32_t* a, const uint32_t* b) {
    asm volatile("mma.sync.aligned.m16n8k16.row.col.f32.bf16.bf16.f32 "
                 "{%0,%1,%2,%3}, {%4,%5,%6,%7}, {%8,%9}, {%0,%1,%2,%3};"
                 : "+f"(c[0]), "+f"(c[1]), "+f"(c[2]), "+f"(c[3])
                 : "r"(a[0]), "r"(a[1]), "r"(a[2]), "r"(a[3]), "r"(b[0]), "r"(b[1]));
}
__device__ __forceinline__ void split2(float v, __nv_bfloat16& hi, __nv_bfloat16& lo) {
    hi = __float2bfloat16(v);
    lo = __float2bfloat16(v - __bfloat162float(hi));
}
template <int EPI>
__device__ __forceinline__ float epi_f(float t) {
    if (EPI == 1) return t > 0.f ? t + 1.f : __expf(t);   // phi = elu+1
    if (EPI == 2) return fmaxf(t, 0.f);                   // relu
    return t;
}

// ===========================================================================
// HMMA GEMM: out[M,256] = A[M,KDIM] * W[KDIM,256]; W passed transposed
// (Wt[256, KDIM], k-contiguous) as bf16 hi/lo planes. A as bf16 hi/lo planes
// with fixed row length 256 (KDIM=512: second pair of planes = cols 256..511).
// CTA tile 128x128, BK=32, 3-stage cp.async pipeline, 8 warps (4x2), warp
// tile 32x64. acc += Ah*Wh + Ah*Wl + Al*Wh.
// ===========================================================================
#define STAGE_BYTES 40960          // A: 2*128*80, B: 2*128*80
#define APLANE      10240
#define GEMM_SMEM   (3 * STAGE_BYTES)

template <int KDIM, int EPI, int OUTM>
__global__ __launch_bounds__(256, 1)
void gemm_mma(const __nv_bfloat16* __restrict__ A0h, const __nv_bfloat16* __restrict__ A0l,
              const __nv_bfloat16* __restrict__ A1h, const __nv_bfloat16* __restrict__ A1l,
              const __nv_bfloat16* __restrict__ Bh,  const __nv_bfloat16* __restrict__ Bl,
              float* __restrict__ outF,
              __nv_bfloat16* __restrict__ outH, __nv_bfloat16* __restrict__ outL)
{
    extern __shared__ char dsm[];
    const uint32_t sb = smem_u32(dsm);

    const int tid    = threadIdx.x;
    const int wid    = tid >> 5;
    const int lane   = tid & 31;
    const int warp_m = wid >> 1;          // 0..3
    const int warp_n = wid & 1;           // 0..1
    const int n0     = blockIdx.x * 128;
    const int m0     = blockIdx.y * 128;
    constexpr int NIT = KDIM / 32;

    // per-thread load slots: 8 chunks of 16B (A: 4, B: 4)
    const int c2   = tid;                 // 0..255
    const int arow = c2 >> 1;             // 0..127
    const int acc4 = (c2 & 1) * 2;        // chunk col pair base (0 or 2)
    const int brow = arow;
    // A chunks: thread covers (plane 0..1) x (cc acc4, acc4+1)? use explicit:
    //   per thread: 4 A chunks = 2 planes x 2 cols ; 4 B chunks likewise.

    float acc[2][8][4];
#pragma unroll
    for (int mt = 0; mt < 2; ++mt)
#pragma unroll
        for (int nt = 0; nt < 8; ++nt)
#pragma unroll
            for (int q = 0; q < 4; ++q) acc[mt][nt][q] = 0.f;

    auto load_stage = [&](int buf, int it) {
        const uint32_t st = sb + buf * STAGE_BYTES;
        const int kc = it * 32;
        const __nv_bfloat16 *Ah, *Al;
        int kk = kc;
        if (KDIM == 512 && kc >= 256) { Ah = A1h; Al = A1l; kk = kc - 256; }
        else                          { Ah = A0h; Al = A0l; }
#pragma unroll
        for (int p = 0; p < 2; ++p) {
            const __nv_bfloat16* ap = p ? Al : Ah;
#pragma unroll
            for (int j = 0; j < 2; ++j) {
                const int cc = acc4 + j;  // 0..3
                cp16(st + p * APLANE + arow * 80 + cc * 16,
                     ap + (size_t)(m0 + arow) * 256 + kk + cc * 8);
            }
        }
        const uint32_t stB = st + 2 * APLANE;
#pragma unroll
        for (int p = 0; p < 2; ++p) {
            const __nv_bfloat16* bp = p ? Bl : Bh;
#pragma unroll
            for (int j = 0; j < 2; ++j) {
                const int cc = acc4 + j;
                cp16(stB + p * APLANE + brow * 80 + cc * 16,
                     bp + (size_t)(n0 + brow) * KDIM + kc + cc * 8);
            }
        }
    };

    load_stage(0, 0); CP_COMMIT();
    load_stage(1, 1); CP_COMMIT();

    const int g  = lane >> 3;
    const int li = lane & 7;
    // ldmatrix lane-address components
    const int a_r  = li + (g & 1) * 8;         // row within m16 tile
    const int a_kb = (g >> 1) * 16;            // k-byte within k16
    const int b_r  = li + (g >> 1) * 8;        // n within n16 group
    const int b_kb = (g & 1) * 16;

    for (int it = 0; it < NIT; ++it) {
        CP_WAIT1();
        __syncthreads();
        if (it + 2 < NIT) load_stage((it + 2) % 3, it + 2);
        CP_COMMIT();

        const uint32_t st  = sb + (it % 3) * STAGE_BYTES;
        const uint32_t stB = st + 2 * APLANE;

#pragma unroll
        for (int ks = 0; ks < 2; ++ks) {
            uint32_t aH[2][4], aL[2][4];
#pragma unroll
            for (int mt = 0; mt < 2; ++mt) {
                const uint32_t ro = (uint32_t)((warp_m * 32 + mt * 16 + a_r) * 80 + ks * 32 + a_kb);
                ldsm4(aH[mt], st + ro);
                ldsm4(aL[mt], st + APLANE + ro);
            }
            uint32_t bH[8][2], bL[8][2];
#pragma unroll
            for (int q = 0; q < 4; ++q) {
                const uint32_t ro = (uint32_t)((warp_n * 64 + q * 16 + b_r) * 80 + ks * 32 + b_kb);
                uint32_t t[4];
                ldsm4(t, stB + ro);
                bH[q * 2][0] = t[0]; bH[q * 2][1] = t[1];
                bH[q * 2 + 1][0] = t[2]; bH[q * 2 + 1][1] = t[3];
                ldsm4(t, stB + APLANE + ro);
                bL[q * 2][0] = t[0]; bL[q * 2][1] = t[1];
                bL[q * 2 + 1][0] = t[2]; bL[q * 2 + 1][1] = t[3];
            }
#pragma unroll
            for (int mt = 0; mt < 2; ++mt)
#pragma unroll
                for (int nt = 0; nt < 8; ++nt) {
                    mma_bf16(acc[mt][nt], aH[mt], bH[nt]);
                    mma_bf16(acc[mt][nt], aH[mt], bL[nt]);
                    mma_bf16(acc[mt][nt], aL[mt], bH[nt]);
                }
        }
        __syncthreads();
    }

    // ------------------------- epilogue -----------------------------------
    const int orow = m0 + warp_m * 32 + (lane >> 2);
    const int ocol = n0 + warp_n * 64 + (lane & 3) * 2;
#pragma unroll
    for (int mt = 0; mt < 2; ++mt) {
#pragma unroll
        for (int nt = 0; nt < 8; ++nt) {
            const int r = orow + mt * 16;
            const int c = ocol + nt * 8;
            float v0 = epi_f<EPI>(acc[mt][nt][0]);
            float v1 = epi_f<EPI>(acc[mt][nt][1]);
            float v2 = epi_f<EPI>(acc[mt][nt][2]);
            float v3 = epi_f<EPI>(acc[mt][nt][3]);
            if (OUTM == 0) {
                float2 u0; u0.x = v0; u0.y = v1;
                float2 u1; u1.x = v2; u1.y = v3;
                *(float2*)&outF[(size_t)r * 256 + c]       = u0;
                *(float2*)&outF[(size_t)(r + 8) * 256 + c] = u1;
            } else {
                __nv_bfloat16 h0, h1, h2, h3, l0, l1, l2, l3;
                split2(v0, h0, l0); split2(v1, h1, l1);
                split2(v2, h2, l2); split2(v3, h3, l3);
                *(__nv_bfloat162*)&outH[(size_t)r * 256 + c]       = __halves2bfloat162(h0, h1);
                *(__nv_bfloat162*)&outH[(size_t)(r + 8) * 256 + c] = __halves2bfloat162(h2, h3);
                *(__nv_bfloat162*)&outL[(size_t)r * 256 + c]       = __halves2bfloat162(l0, l1);
                *(__nv_bfloat162*)&outL[(size_t)(r + 8) * 256 + c] = __halves2bfloat162(l2, l3);
            }
        }
    }
}

// ===========================================================================
// aux kernels
// ===========================================================================
__global__ void split_kernel(const float* __restrict__ in,
                             __nv_bfloat16* __restrict__ hi,
                             __nv_bfloat16* __restrict__ lo, int n4)
{
    int i = blockIdx.x * blockDim.x + threadIdx.x;
    if (i >= n4) return;
    float4 v = ((const float4*)in)[i];
    __nv_bfloat16 h0, h1, h2, h3, l0, l1, l2, l3;
    split2(v.x, h0, l0); split2(v.y, h1, l1); split2(v.z, h2, l2); split2(v.w, h3, l3);
    ((__nv_bfloat162*)hi)[i * 2 + 0] = __halves2bfloat162(h0, h1);
    ((__nv_bfloat162*)hi)[i * 2 + 1] = __halves2bfloat162(h2, h3);
    ((__nv_bfloat162*)lo)[i * 2 + 0] = __halves2bfloat162(l0, l1);
    ((__nv_bfloat162*)lo)[i * 2 + 1] = __halves2bfloat162(l2, l3);
}

__global__ void wprep_kernel(const float* __restrict__ W,
                             __nv_bfloat16* __restrict__ hi,
                             __nv_bfloat16* __restrict__ lo, int K, int N)
{
    int idx = blockIdx.x * blockDim.x + threadIdx.x;
    if (idx >= K * N) return;
    int nn = idx / K, kk = idx % K;
    split2(W[(size_t)kk * N + nn], hi[idx], lo[idx]);
}

__global__ void zero_kernel(float* p, int n)
{
    int i = blockIdx.x * blockDim.x + threadIdx.x;
    if (i < n) p[i] = 0.f;
}

__global__ __launch_bounds__(1024) void kv_reduce_kernel(
    const float* __restrict__ Kp, const float* __restrict__ Vp,
    float* __restrict__ KV, float* __restrict__ Ksum, int L)
{
    const int nh = blockIdx.x;
    const int n  = nh >> 3;
    const int h  = nh & 7;
    const int rows = L / gridDim.y;
    const int l0 = blockIdx.y * rows;
    const int tid = threadIdx.x;
    const int d = tid >> 5;
    const int e = tid & 31;

    __shared__ float sk[16][32];
    __shared__ float sv[16][32];

    const size_t base = (size_t)n * L * 256 + h * 32;
    const int ldrow = tid >> 6;
    const int ldc   = tid & 63;

    float acc = 0.f, ks = 0.f;
    for (int l = l0; l < l0 + rows; l += 16) {
        __syncthreads();
        {
            size_t off = base + (size_t)(l + ldrow) * 256;
            if (ldc < 32) sk[ldrow][ldc] = Kp[off + ldc];
            else          sv[ldrow][ldc - 32] = Vp[off + ldc - 32];
        }
        __syncthreads();
#pragma unroll
        for (int r = 0; r < 16; ++r) acc += sk[r][d] * sv[r][e];
        if (e == 0) {
#pragma unroll
            for (int r = 0; r < 16; ++r) ks += sk[r][d];
        }
    }
    atomicAdd(&KV[(size_t)nh * 1024 + d * 32 + e], acc);
    if (e == 0) atomicAdd(&Ksum[nh * 32 + d], ks);
}

__global__ __launch_bounds__(256) void msg_kernel(
    const float* __restrict__ Q, const float* __restrict__ KV,
    const float* __restrict__ Ksum,
    __nv_bfloat16* __restrict__ MH, __nv_bfloat16* __restrict__ ML, int L)
{
    const int row = blockIdx.x;
    const int n = row / L;
    const int tid = threadIdx.x;
    const int h = tid >> 5;
    const int e = tid & 31;

    __shared__ float qs[256];
    qs[tid] = Q[(size_t)row * 256 + tid];
    __syncthreads();

    float p = qs[h * 32 + e] * Ksum[(n * 8 + h) * 32 + e];
#pragma unroll
    for (int o = 16; o; o >>= 1) p += __shfl_xor_sync(0xffffffffu, p, o);
    const float z = 1.f / (p + 1e-6f);

    const float* kv = KV + (size_t)(n * 8 + h) * 1024;
    float acc = 0.f;
#pragma unroll
    for (int dd = 0; dd < 32; ++dd) acc += qs[h * 32 + dd] * kv[dd * 32 + e];

    split2(acc * z, MH[(size_t)row * 256 + tid], ML[(size_t)row * 256 + tid]);
}

template <int OUT>
__global__ __launch_bounds__(256) void ln_kernel(
    const float* __restrict__ in, const float* __restrict__ res,
    const float* __restrict__ g, const float* __restrict__ b,
    float* __restrict__ outf,
    __nv_bfloat16* __restrict__ oh, __nv_bfloat16* __restrict__ ol, int rows)
{
    const int gw = (int)((blockIdx.x * blockDim.x + threadIdx.x) >> 5);
    if (gw >= rows) return;
    const int lane = threadIdx.x & 31;

    const float4* rp = (const float4*)(in + (size_t)gw * 256);
    float v[8];
    *(float4*)&v[0] = rp[lane];
    *(float4*)&v[4] = rp[lane + 32];

    float s = 0.f;
#pragma unroll
    for (int i = 0; i < 8; ++i) s += v[i];
#pragma unroll
    for (int o = 16; o; o >>= 1) s += __shfl_xor_sync(0xffffffffu, s, o);
    const float mu = s * (1.f / 256.f);

    float vs = 0.f;
#pragma unroll
    for (int i = 0; i < 8; ++i) { v[i] -= mu; vs += v[i] * v[i]; }
#pragma unroll
    for (int o = 16; o; o >>= 1) vs += __shfl_xor_sync(0xffffffffu, vs, o);
    const float rstd = rsqrtf(vs * (1.f / 256.f) + 1e-5f);

    float G[8], Bv[8];
    *(float4*)&G[0]  = ((const float4*)g)[lane];
    *(float4*)&G[4]  = ((const float4*)g)[lane + 32];
    *(float4*)&Bv[0] = ((const float4*)b)[lane];
    *(float4*)&Bv[4] = ((const float4*)b)[lane + 32];

    float o8[8];
#pragma unroll
    for (int i = 0; i < 8; ++i) o8[i] = v[i] * rstd * G[i] + Bv[i];

    if (OUT == 0) {
        if (res) {
            const float4* xp = (const float4*)(res + (size_t)gw * 256);
            float r8[8];
            *(float4*)&r8[0] = xp[lane];
            *(float4*)&r8[4] = xp[lane + 32];
#pragma unroll
            for (int i = 0; i < 8; ++i) o8[i] += r8[i];
        }
        float4* op = (float4*)(outf + (size_t)gw * 256);
        op[lane]      = *(float4*)&o8[0];
        op[lane + 32] = *(float4*)&o8[4];
    } else {
        __nv_bfloat16 h[8], l[8];
#pragma unroll
        for (int i = 0; i < 8; ++i) split2(o8[i], h[i], l[i]);
        __nv_bfloat162* ph0 = (__nv_bfloat162*)(oh + (size_t)gw * 256 + lane * 4);
        __nv_bfloat162* ph1 = (__nv_bfloat162*)(oh + (size_t)gw * 256 + 128 + lane * 4);
        __nv_bfloat162* pl0 = (__nv_bfloat162*)(ol + (size_t)gw * 256 + lane * 4);
        __nv_bfloat162* pl1 = (__nv_bfloat162*)(ol + (size_t)gw * 256 + 128 + lane * 4);
        ph0[0] = __halves2bfloat162(h[0], h[1]); ph0[1] = __halves2bfloat162(h[2], h[3]);
        ph1[0] = __halves2bfloat162(h[4], h[5]); ph1[1] = __halves2bfloat162(h[6], h[7]);
        pl0[0] = __halves2bfloat162(l[0], l[1]); pl0[1] = __halves2bfloat162(l[2], l[3]);
        pl1[0] = __halves2bfloat162(l[4], l[5]); pl1[1] = __halves2bfloat162(l[6], l[7]);
    }
}

// ===========================================================================
// launch
// ===========================================================================
extern "C" void kernel_launch(void* const* d_in, const int* in_sizes, int n_in,
                              void* d_out, int out_size)
{
    const float* x  = (const float*)d_in[0];
    const float* Wq = (const float*)d_in[1];
    const float* Wk = (const float*)d_in[2];
    const float* Wv = (const float*)d_in[3];
    const float* Wm = (const float*)d_in[4];
    const float* W1 = (const float*)d_in[5];
    const float* W2 = (const float*)d_in[6];
    const float* g1 = (const float*)d_in[7];
    const float* b1 = (const float*)d_in[8];
    const float* g2 = (const float*)d_in[9];
    const float* b2 = (const float*)d_in[10];

    const int M = in_sizes[0] / C_DIM;   // 65536
    const int L = M / NB;                // 16384

    float *Qf, *Kf, *Vf, *sm;
    __nv_bfloat16 *xhi, *xlo, *mhi, *mlo, *lhi, *llo, *hhi, *hlo, *gw;
    cudaGetSymbolAddress((void**)&Qf, g_Q);
    cudaGetSymbolAddress((void**)&Kf, g_K);
    cudaGetSymbolAddress((void**)&Vf, g_V);
    cudaGetSymbolAddress((void**)&xhi, g_xhi);
    cudaGetSymbolAddress((void**)&xlo, g_xlo);
    cudaGetSymbolAddress((void**)&mhi, g_mhi);
    cudaGetSymbolAddress((void**)&mlo, g_mlo);
    cudaGetSymbolAddress((void**)&lhi, g_lhi);
    cudaGetSymbolAddress((void**)&llo, g_llo);
    cudaGetSymbolAddress((void**)&hhi, g_hhi);
    cudaGetSymbolAddress((void**)&hlo, g_hlo);
    cudaGetSymbolAddress((void**)&gw, g_w);
    cudaGetSymbolAddress((void**)&sm, g_small);
    float* KV   = sm;
    float* Ksum = sm + 32 * 1024;

    __nv_bfloat16 *wqh = gw,           *wql = gw + 65536;
    __nv_bfloat16 *wkh = gw + 131072,  *wkl = gw + 196608;
    __nv_bfloat16 *wvh = gw + 262144,  *wvl = gw + 327680;
    __nv_bfloat16 *wmh = gw + 393216,  *wml = gw + 458752;
    __nv_bfloat16 *w2h = gw + 524288,  *w2l = gw + 589824;
    __nv_bfloat16 *w1h = gw + 655360,  *w1l = gw + 786432;

    cudaFuncSetAttribute(gemm_mma<256, 1, 0>, cudaFuncAttributeMaxDynamicSharedMemorySize, GEMM_SMEM);
    cudaFuncSetAttribute(gemm_mma<256, 0, 0>, cudaFuncAttributeMaxDynamicSharedMemorySize, GEMM_SMEM);
    cudaFuncSetAttribute(gemm_mma<512, 2, 1>, cudaFuncAttributeMaxDynamicSharedMemorySize, GEMM_SMEM);

    wprep_kernel<<<256, 256>>>(Wq, wqh, wql, 256, 256);
    wprep_kernel<<<256, 256>>>(Wk, wkh, wkl, 256, 256);
    wprep_kernel<<<256, 256>>>(Wv, wvh, wvl, 256, 256);
    wprep_kernel<<<256, 256>>>(Wm, wmh, wml, 256, 256);
    wprep_kernel<<<256, 256>>>(W2, w2h, w2l, 256, 256);
    wprep_kernel<<<512, 256>>>(W1, w1h, w1l, 512, 256);
    split_kernel<<<(M * 64 + 255) / 256, 256>>>(x, xhi, xlo, M * 64);

    dim3 gg(2, M / 128);   // (N tiles, M tiles)

    gemm_mma<256, 1, 0><<<gg, 256, GEMM_SMEM>>>(xhi, xlo, nullptr, nullptr, wqh, wql, Qf, nullptr, nullptr);
    gemm_mma<256, 1, 0><<<gg, 256, GEMM_SMEM>>>(xhi, xlo, nullptr, nullptr, wkh, wkl, Kf, nullptr, nullptr);
    gemm_mma<256, 0, 0><<<gg, 256, GEMM_SMEM>>>(xhi, xlo, nullptr, nullptr, wvh, wvl, Vf, nullptr, nullptr);

    zero_kernel<<<(33792 + 255) / 256, 256>>>(sm, 33792);
    kv_reduce_kernel<<<dim3(32, 64), 1024>>>(Kf, Vf, KV, Ksum, L);

    msg_kernel<<<M, 256>>>(Qf, KV, Ksum, mhi, mlo, L);

    gemm_mma<256, 0, 0><<<gg, 256, GEMM_SMEM>>>(mhi, mlo, nullptr, nullptr, wmh, wml, Kf, nullptr, nullptr);
    ln_kernel<1><<<M / 8, 256>>>(Kf, nullptr, g1, b1, nullptr, lhi, llo, M);

    gemm_mma<512, 2, 1><<<gg, 256, GEMM_SMEM>>>(xhi, xlo, lhi, llo, w1h, w1l, nullptr, hhi, hlo);

    gemm_mma<256, 0, 0><<<gg, 256, GEMM_SMEM>>>(hhi, hlo, nullptr, nullptr, w2h, w2l, Vf, nullptr, nullptr);
    ln_kernel<0><<<M / 8, 256>>>(Vf, x, g2, b2, (float*)d_out, nullptr, nullptr, M);
}

// round 4
// speedup vs baseline: 1.4686x; 1.0025x over previous
#include <cuda_runtime.h>
#include <cuda_bf16.h>
#include <cstdint>
#include <cstddef>

// ===========================================================================
// StructureAttention, tensor cores via mma.sync (bf16 hi/lo x3, fp32 accum).
// R4: plane-major MMA ordering (16 independent accumulators between RAW
// reuse) to remove dependent-HMMA latency stalls.
// ===========================================================================

#define C_DIM 256
#define NB    4
#define MTOT  16777216

__device__ float g_Q[MTOT];
__device__ float g_K[MTOT];
__device__ float g_V[MTOT];
__device__ __nv_bfloat16 g_xhi[MTOT], g_xlo[MTOT];
__device__ __nv_bfloat16 g_mhi[MTOT], g_mlo[MTOT];
__device__ __nv_bfloat16 g_lhi[MTOT], g_llo[MTOT];
__device__ __nv_bfloat16 g_hhi[MTOT], g_hlo[MTOT];
__device__ __nv_bfloat16 g_w[917504];
__device__ float g_small[32 * 1024 + 32 * 32];

// ---------------- helpers --------------------------------------------------
__device__ __forceinline__ uint32_t smem_u32(const void* p) {
    uint32_t a;
    asm("{ .reg .u64 t; cvta.to.shared.u64 t, %1; cvt.u32.u64 %0, t; }" : "=r"(a) : "l"(p));
    return a;
}
__device__ __forceinline__ void cp16(uint32_t dst, const void* src) {
    asm volatile("cp.async.cg.shared.global [%0], [%1], 16;"
                 :: "r"(dst), "l"(__cvta_generic_to_global(src)) : "memory");
}
#define CP_COMMIT() asm volatile("cp.async.commit_group;" ::: "memory")
#define CP_WAIT1()  asm volatile("cp.async.wait_group 1;"  ::: "memory")

__device__ __forceinline__ void ldsm4(uint32_t* r, uint32_t addr) {
    asm volatile("ldmatrix.sync.aligned.m8n8.x4.shared.b16 {%0,%1,%2,%3}, [%4];"
                 : "=r"(r[0]), "=r"(r[1]), "=r"(r[2]), "=r"(r[3]) : "r"(addr));
}
// NOTE: non-volatile — pure register op, lets ptxas schedule/interleave.
__device__ __forceinline__ void mma_bf16(float* c, const uint32_t* a, const uint32_t* b) {
    asm("mma.sync.aligned.m16n8k16.row.col.f32.bf16.bf16.f32 "
        "{%0,%1,%2,%3}, {%4,%5,%6,%7}, {%8,%9}, {%0,%1,%2,%3};"
        : "+f"(c[0]), "+f"(c[1]), "+f"(c[2]), "+f"(c[3])
        : "r"(a[0]), "r"(a[1]), "r"(a[2]), "r"(a[3]), "r"(b[0]), "r"(b[1]));
}
__device__ __forceinline__ void split2(float v, __nv_bfloat16& hi, __nv_bfloat16& lo) {
    hi = __float2bfloat16(v);
    lo = __float2bfloat16(v - __bfloat162float(hi));
}
template <int EPI>
__device__ __forceinline__ float epi_f(float t) {
    if (EPI == 1) return t > 0.f ? t + 1.f : __expf(t);   // phi = elu+1
    if (EPI == 2) return fmaxf(t, 0.f);                   // relu
    return t;
}

// ===========================================================================
// HMMA GEMM: out[M,256] = A[M,KDIM] * W[KDIM,256]; W transposed
// (Wt[256,KDIM]) as bf16 hi/lo planes; A as bf16 hi/lo planes (row len 256;
// KDIM=512 -> second plane pair is cols 256..511).
// CTA 128x128, BK=32, 3-stage cp.async, 8 warps (4x2), warp tile 32x64.
// acc += Ah*Wh + Ah*Wl + Al*Wh   (plane-major issue order)
// ===========================================================================
#define STAGE_BYTES 40960          // A: 2*128*80, B: 2*128*80
#define APLANE      10240
#define GEMM_SMEM   (3 * STAGE_BYTES)

template <int KDIM, int EPI, int OUTM>
__global__ __launch_bounds__(256, 1)
void gemm_mma(const __nv_bfloat16* __restrict__ A0h, const __nv_bfloat16* __restrict__ A0l,
              const __nv_bfloat16* __restrict__ A1h, const __nv_bfloat16* __restrict__ A1l,
              const __nv_bfloat16* __restrict__ Bh,  const __nv_bfloat16* __restrict__ Bl,
              float* __restrict__ outF,
              __nv_bfloat16* __restrict__ outH, __nv_bfloat16* __restrict__ outL)
{
    extern __shared__ char dsm[];
    const uint32_t sb = smem_u32(dsm);

    const int tid    = threadIdx.x;
    const int lane   = tid & 31;
    const int wid    = tid >> 5;
    const int warp_m = wid >> 1;          // 0..3
    const int warp_n = wid & 1;           // 0..1
    const int n0     = blockIdx.x * 128;
    const int m0     = blockIdx.y * 128;
    constexpr int NIT = KDIM / 32;

    const int arow = tid >> 1;            // 0..127
    const int acc4 = (tid & 1) * 2;       // 16B-chunk col base (0 or 2)

    float acc[2][8][4];
#pragma unroll
    for (int mt = 0; mt < 2; ++mt)
#pragma unroll
        for (int nt = 0; nt < 8; ++nt)
#pragma unroll
            for (int q = 0; q < 4; ++q) acc[mt][nt][q] = 0.f;

    auto load_stage = [&](int buf, int it) {
        const uint32_t st = sb + buf * STAGE_BYTES;
        const int kc = it * 32;
        const __nv_bfloat16 *Ah, *Al;
        int kk = kc;
        if (KDIM == 512 && kc >= 256) { Ah = A1h; Al = A1l; kk = kc - 256; }
        else                          { Ah = A0h; Al = A0l; }
#pragma unroll
        for (int p = 0; p < 2; ++p) {
            const __nv_bfloat16* ap = p ? Al : Ah;
#pragma unroll
            for (int j = 0; j < 2; ++j) {
                const int cc = acc4 + j;
                cp16(st + p * APLANE + arow * 80 + cc * 16,
                     ap + (size_t)(m0 + arow) * 256 + kk + cc * 8);
            }
        }
        const uint32_t stB = st + 2 * APLANE;
#pragma unroll
        for (int p = 0; p < 2; ++p) {
            const __nv_bfloat16* bp = p ? Bl : Bh;
#pragma unroll
            for (int j = 0; j < 2; ++j) {
                const int cc = acc4 + j;
                cp16(stB + p * APLANE + arow * 80 + cc * 16,
                     bp + (size_t)(n0 + arow) * KDIM + kc + cc * 8);
            }
        }
    };

    load_stage(0, 0); CP_COMMIT();
    load_stage(1, 1); CP_COMMIT();

    const int g  = lane >> 3;
    const int li = lane & 7;
    const int a_r  = li + (g & 1) * 8;
    const int a_kb = (g >> 1) * 16;
    const int b_r  = li + (g >> 1) * 8;
    const int b_kb = (g & 1) * 16;

    for (int it = 0; it < NIT; ++it) {
        CP_WAIT1();
        __syncthreads();
        if (it + 2 < NIT) load_stage((it + 2) % 3, it + 2);
        CP_COMMIT();

        const uint32_t st  = sb + (it % 3) * STAGE_BYTES;
        const uint32_t stB = st + 2 * APLANE;

#pragma unroll
        for (int ks = 0; ks < 2; ++ks) {
            uint32_t aH[2][4], aL[2][4];
#pragma unroll
            for (int mt = 0; mt < 2; ++mt) {
                const uint32_t ro = (uint32_t)((warp_m * 32 + mt * 16 + a_r) * 80 + ks * 32 + a_kb);
                ldsm4(aH[mt], st + ro);
                ldsm4(aL[mt], st + APLANE + ro);
            }
            uint32_t bH[8][2], bL[8][2];
#pragma unroll
            for (int q = 0; q < 4; ++q) {
                const uint32_t ro = (uint32_t)((warp_n * 64 + q * 16 + b_r) * 80 + ks * 32 + b_kb);
                uint32_t t[4];
                ldsm4(t, stB + ro);
                bH[q * 2][0] = t[0]; bH[q * 2][1] = t[1];
                bH[q * 2 + 1][0] = t[2]; bH[q * 2 + 1][1] = t[3];
                ldsm4(t, stB + APLANE + ro);
                bL[q * 2][0] = t[0]; bL[q * 2][1] = t[1];
                bL[q * 2 + 1][0] = t[2]; bL[q * 2 + 1][1] = t[3];
            }
            // plane-major: 16 independent accumulators between RAW reuse
#pragma unroll
            for (int mt = 0; mt < 2; ++mt)
#pragma unroll
                for (int nt = 0; nt < 8; ++nt)
                    mma_bf16(acc[mt][nt], aH[mt], bH[nt]);
#pragma unroll
            for (int mt = 0; mt < 2; ++mt)
#pragma unroll
                for (int nt = 0; nt < 8; ++nt)
                    mma_bf16(acc[mt][nt], aH[mt], bL[nt]);
#pragma unroll
            for (int mt = 0; mt < 2; ++mt)
#pragma unroll
                for (int nt = 0; nt < 8; ++nt)
                    mma_bf16(acc[mt][nt], aL[mt], bH[nt]);
        }
        __syncthreads();
    }

    // ------------------------- epilogue -----------------------------------
    const int orow = m0 + warp_m * 32 + (lane >> 2);
    const int ocol = n0 + warp_n * 64 + (lane & 3) * 2;
#pragma unroll
    for (int mt = 0; mt < 2; ++mt) {
#pragma unroll
        for (int nt = 0; nt < 8; ++nt) {
            const int r = orow + mt * 16;
            const int c = ocol + nt * 8;
            float v0 = epi_f<EPI>(acc[mt][nt][0]);
            float v1 = epi_f<EPI>(acc[mt][nt][1]);
            float v2 = epi_f<EPI>(acc[mt][nt][2]);
            float v3 = epi_f<EPI>(acc[mt][nt][3]);
            if (OUTM == 0) {
                float2 u0; u0.x = v0; u0.y = v1;
                float2 u1; u1.x = v2; u1.y = v3;
                *(float2*)&outF[(size_t)r * 256 + c]       = u0;
                *(float2*)&outF[(size_t)(r + 8) * 256 + c] = u1;
            } else {
                __nv_bfloat16 h0, h1, h2, h3, l0, l1, l2, l3;
                split2(v0, h0, l0); split2(v1, h1, l1);
                split2(v2, h2, l2); split2(v3, h3, l3);
                *(__nv_bfloat162*)&outH[(size_t)r * 256 + c]       = __halves2bfloat162(h0, h1);
                *(__nv_bfloat162*)&outH[(size_t)(r + 8) * 256 + c] = __halves2bfloat162(h2, h3);
                *(__nv_bfloat162*)&outL[(size_t)r * 256 + c]       = __halves2bfloat162(l0, l1);
                *(__nv_bfloat162*)&outL[(size_t)(r + 8) * 256 + c] = __halves2bfloat162(l2, l3);
            }
        }
    }
}

// ===========================================================================
// aux kernels
// ===========================================================================
__global__ void split_kernel(const float* __restrict__ in,
                             __nv_bfloat16* __restrict__ hi,
                             __nv_bfloat16* __restrict__ lo, int n4)
{
    int i = blockIdx.x * blockDim.x + threadIdx.x;
    if (i >= n4) return;
    float4 v = ((const float4*)in)[i];
    __nv_bfloat16 h0, h1, h2, h3, l0, l1, l2, l3;
    split2(v.x, h0, l0); split2(v.y, h1, l1); split2(v.z, h2, l2); split2(v.w, h3, l3);
    ((__nv_bfloat162*)hi)[i * 2 + 0] = __halves2bfloat162(h0, h1);
    ((__nv_bfloat162*)hi)[i * 2 + 1] = __halves2bfloat162(h2, h3);
    ((__nv_bfloat162*)lo)[i * 2 + 0] = __halves2bfloat162(l0, l1);
    ((__nv_bfloat162*)lo)[i * 2 + 1] = __halves2bfloat162(l2, l3);
}

__global__ void wprep_kernel(const float* __restrict__ W,
                             __nv_bfloat16* __restrict__ hi,
                             __nv_bfloat16* __restrict__ lo, int K, int N)
{
    int idx = blockIdx.x * blockDim.x + threadIdx.x;
    if (idx >= K * N) return;
    int nn = idx / K, kk = idx % K;
    split2(W[(size_t)kk * N + nn], hi[idx], lo[idx]);
}

__global__ void zero_kernel(float* p, int n)
{
    int i = blockIdx.x * blockDim.x + threadIdx.x;
    if (i < n) p[i] = 0.f;
}

__global__ __launch_bounds__(1024) void kv_reduce_kernel(
    const float* __restrict__ Kp, const float* __restrict__ Vp,
    float* __restrict__ KV, float* __restrict__ Ksum, int L)
{
    const int nh = blockIdx.x;
    const int n  = nh >> 3;
    const int h  = nh & 7;
    const int rows = L / gridDim.y;
    const int l0 = blockIdx.y * rows;
    const int tid = threadIdx.x;
    const int d = tid >> 5;
    const int e = tid & 31;

    __shared__ float sk[16][32];
    __shared__ float sv[16][32];

    const size_t base = (size_t)n * L * 256 + h * 32;
    const int ldrow = tid >> 6;
    const int ldc   = tid & 63;

    float acc = 0.f, ks = 0.f;
    for (int l = l0; l < l0 + rows; l += 16) {
        __syncthreads();
        {
            size_t off = base + (size_t)(l + ldrow) * 256;
            if (ldc < 32) sk[ldrow][ldc] = Kp[off + ldc];
            else          sv[ldrow][ldc - 32] = Vp[off + ldc - 32];
        }
        __syncthreads();
#pragma unroll
        for (int r = 0; r < 16; ++r) acc += sk[r][d] * sv[r][e];
        if (e == 0) {
#pragma unroll
            for (int r = 0; r < 16; ++r) ks += sk[r][d];
        }
    }
    atomicAdd(&KV[(size_t)nh * 1024 + d * 32 + e], acc);
    if (e == 0) atomicAdd(&Ksum[nh * 32 + d], ks);
}

__global__ __launch_bounds__(256) void msg_kernel(
    const float* __restrict__ Q, const float* __restrict__ KV,
    const float* __restrict__ Ksum,
    __nv_bfloat16* __restrict__ MH, __nv_bfloat16* __restrict__ ML, int L)
{
    const int row = blockIdx.x;
    const int n = row / L;
    const int tid = threadIdx.x;
    const int h = tid >> 5;
    const int e = tid & 31;

    __shared__ float qs[256];
    qs[tid] = Q[(size_t)row * 256 + tid];
    __syncthreads();

    float p = qs[h * 32 + e] * Ksum[(n * 8 + h) * 32 + e];
#pragma unroll
    for (int o = 16; o; o >>= 1) p += __shfl_xor_sync(0xffffffffu, p, o);
    const float z = 1.f / (p + 1e-6f);

    const float* kv = KV + (size_t)(n * 8 + h) * 1024;
    float acc = 0.f;
#pragma unroll
    for (int dd = 0; dd < 32; ++dd) acc += qs[h * 32 + dd] * kv[dd * 32 + e];

    split2(acc * z, MH[(size_t)row * 256 + tid], ML[(size_t)row * 256 + tid]);
}

template <int OUT>
__global__ __launch_bounds__(256) void ln_kernel(
    const float* __restrict__ in, const float* __restrict__ res,
    const float* __restrict__ g, const float* __restrict__ b,
    float* __restrict__ outf,
    __nv_bfloat16* __restrict__ oh, __nv_bfloat16* __restrict__ ol, int rows)
{
    const int gw = (int)((blockIdx.x * blockDim.x + threadIdx.x) >> 5);
    if (gw >= rows) return;
    const int lane = threadIdx.x & 31;

    const float4* rp = (const float4*)(in + (size_t)gw * 256);
    float v[8];
    *(float4*)&v[0] = rp[lane];
    *(float4*)&v[4] = rp[lane + 32];

    float s = 0.f;
#pragma unroll
    for (int i = 0; i < 8; ++i) s += v[i];
#pragma unroll
    for (int o = 16; o; o >>= 1) s += __shfl_xor_sync(0xffffffffu, s, o);
    const float mu = s * (1.f / 256.f);

    float vs = 0.f;
#pragma unroll
    for (int i = 0; i < 8; ++i) { v[i] -= mu; vs += v[i] * v[i]; }
#pragma unroll
    for (int o = 16; o; o >>= 1) vs += __shfl_xor_sync(0xffffffffu, vs, o);
    const float rstd = rsqrtf(vs * (1.f / 256.f) + 1e-5f);

    float G[8], Bv[8];
    *(float4*)&G[0]  = ((const float4*)g)[lane];
    *(float4*)&G[4]  = ((const float4*)g)[lane + 32];
    *(float4*)&Bv[0] = ((const float4*)b)[lane];
    *(float4*)&Bv[4] = ((const float4*)b)[lane + 32];

    float o8[8];
#pragma unroll
    for (int i = 0; i < 8; ++i) o8[i] = v[i] * rstd * G[i] + Bv[i];

    if (OUT == 0) {
        if (res) {
            const float4* xp = (const float4*)(res + (size_t)gw * 256);
            float r8[8];
            *(float4*)&r8[0] = xp[lane];
            *(float4*)&r8[4] = xp[lane + 32];
#pragma unroll
            for (int i = 0; i < 8; ++i) o8[i] += r8[i];
        }
        float4* op = (float4*)(outf + (size_t)gw * 256);
        op[lane]      = *(float4*)&o8[0];
        op[lane + 32] = *(float4*)&o8[4];
    } else {
        __nv_bfloat16 h[8], l[8];
#pragma unroll
        for (int i = 0; i < 8; ++i) split2(o8[i], h[i], l[i]);
        __nv_bfloat162* ph0 = (__nv_bfloat162*)(oh + (size_t)gw * 256 + lane * 4);
        __nv_bfloat162* ph1 = (__nv_bfloat162*)(oh + (size_t)gw * 256 + 128 + lane * 4);
        __nv_bfloat162* pl0 = (__nv_bfloat162*)(ol + (size_t)gw * 256 + lane * 4);
        __nv_bfloat162* pl1 = (__nv_bfloat162*)(ol + (size_t)gw * 256 + 128 + lane * 4);
        ph0[0] = __halves2bfloat162(h[0], h[1]); ph0[1] = __halves2bfloat162(h[2], h[3]);
        ph1[0] = __halves2bfloat162(h[4], h[5]); ph1[1] = __halves2bfloat162(h[6], h[7]);
        pl0[0] = __halves2bfloat162(l[0], l[1]); pl0[1] = __halves2bfloat162(l[2], l[3]);
        pl1[0] = __halves2bfloat162(l[4], l[5]); pl1[1] = __halves2bfloat162(l[6], l[7]);
    }
}

// ===========================================================================
// launch
// ===========================================================================
extern "C" void kernel_launch(void* const* d_in, const int* in_sizes, int n_in,
                              void* d_out, int out_size)
{
    const float* x  = (const float*)d_in[0];
    const float* Wq = (const float*)d_in[1];
    const float* Wk = (const float*)d_in[2];
    const float* Wv = (const float*)d_in[3];
    const float* Wm = (const float*)d_in[4];
    const float* W1 = (const float*)d_in[5];
    const float* W2 = (const float*)d_in[6];
    const float* g1 = (const float*)d_in[7];
    const float* b1 = (const float*)d_in[8];
    const float* g2 = (const float*)d_in[9];
    const float* b2 = (const float*)d_in[10];

    const int M = in_sizes[0] / C_DIM;   // 65536
    const int L = M / NB;                // 16384

    float *Qf, *Kf, *Vf, *sm;
    __nv_bfloat16 *xhi, *xlo, *mhi, *mlo, *lhi, *llo, *hhi, *hlo, *gw;
    cudaGetSymbolAddress((void**)&Qf, g_Q);
    cudaGetSymbolAddress((void**)&Kf, g_K);
    cudaGetSymbolAddress((void**)&Vf, g_V);
    cudaGetSymbolAddress((void**)&xhi, g_xhi);
    cudaGetSymbolAddress((void**)&xlo, g_xlo);
    cudaGetSymbolAddress((void**)&mhi, g_mhi);
    cudaGetSymbolAddress((void**)&mlo, g_mlo);
    cudaGetSymbolAddress((void**)&lhi, g_lhi);
    cudaGetSymbolAddress((void**)&llo, g_llo);
    cudaGetSymbolAddress((void**)&hhi, g_hhi);
    cudaGetSymbolAddress((void**)&hlo, g_hlo);
    cudaGetSymbolAddress((void**)&gw, g_w);
    cudaGetSymbolAddress((void**)&sm, g_small);
    float* KV   = sm;
    float* Ksum = sm + 32 * 1024;

    __nv_bfloat16 *wqh = gw,           *wql = gw + 65536;
    __nv_bfloat16 *wkh = gw + 131072,  *wkl = gw + 196608;
    __nv_bfloat16 *wvh = gw + 262144,  *wvl = gw + 327680;
    __nv_bfloat16 *wmh = gw + 393216,  *wml = gw + 458752;
    __nv_bfloat16 *w2h = gw + 524288,  *w2l = gw + 589824;
    __nv_bfloat16 *w1h = gw + 655360,  *w1l = gw + 786432;

    cudaFuncSetAttribute(gemm_mma<256, 1, 0>, cudaFuncAttributeMaxDynamicSharedMemorySize, GEMM_SMEM);
    cudaFuncSetAttribute(gemm_mma<256, 0, 0>, cudaFuncAttributeMaxDynamicSharedMemorySize, GEMM_SMEM);
    cudaFuncSetAttribute(gemm_mma<512, 2, 1>, cudaFuncAttributeMaxDynamicSharedMemorySize, GEMM_SMEM);

    wprep_kernel<<<256, 256>>>(Wq, wqh, wql, 256, 256);
    wprep_kernel<<<256, 256>>>(Wk, wkh, wkl, 256, 256);
    wprep_kernel<<<256, 256>>>(Wv, wvh, wvl, 256, 256);
    wprep_kernel<<<256, 256>>>(Wm, wmh, wml, 256, 256);
    wprep_kernel<<<256, 256>>>(W2, w2h, w2l, 256, 256);
    wprep_kernel<<<512, 256>>>(W1, w1h, w1l, 512, 256);
    split_kernel<<<(M * 64 + 255) / 256, 256>>>(x, xhi, xlo, M * 64);

    dim3 gg(2, M / 128);   // (N tiles, M tiles)

    gemm_mma<256, 1, 0><<<gg, 256, GEMM_SMEM>>>(xhi, xlo, nullptr, nullptr, wqh, wql, Qf, nullptr, nullptr);
    gemm_mma<256, 1, 0><<<gg, 256, GEMM_SMEM>>>(xhi, xlo, nullptr, nullptr, wkh, wkl, Kf, nullptr, nullptr);
    gemm_mma<256, 0, 0><<<gg, 256, GEMM_SMEM>>>(xhi, xlo, nullptr, nullptr, wvh, wvl, Vf, nullptr, nullptr);

    zero_kernel<<<(33792 + 255) / 256, 256>>>(sm, 33792);
    kv_reduce_kernel<<<dim3(32, 64), 1024>>>(Kf, Vf, KV, Ksum, L);

    msg_kernel<<<M, 256>>>(Qf, KV, Ksum, mhi, mlo, L);

    gemm_mma<256, 0, 0><<<gg, 256, GEMM_SMEM>>>(mhi, mlo, nullptr, nullptr, wmh, wml, Kf, nullptr, nullptr);
    ln_kernel<1><<<M / 8, 256>>>(Kf, nullptr, g1, b1, nullptr, lhi, llo, M);

    gemm_mma<512, 2, 1><<<gg, 256, GEMM_SMEM>>>(xhi, xlo, lhi, llo, w1h, w1l, nullptr, hhi, hlo);

    gemm_mma<256, 0, 0><<<gg, 256, GEMM_SMEM>>>(hhi, hlo, nullptr, nullptr, w2h, w2l, Vf, nullptr, nullptr);
    ln_kernel<0><<<M / 8, 256>>>(Vf, x, g2, b2, (float*)d_out, nullptr, nullptr, M);
}